// round 1
// baseline (speedup 1.0000x reference)
#include <cuda_runtime.h>
#include <math.h>

// VectorQuantizer: z [N=65536, D=256] f32, codebook W [NE=1024, D=256] f32.
// dist = ||z||^2 - 2 z.W^T + ||w||^2 ; idx = argmin (first-min tie-break)
// outputs (concatenated float32): z_q_st [N*256] | loss [N] | idx [N]
//
// Precision contract: replicate reference fp32 rounding:
//   A = sum_i fl(z_i^2) sequential;  C = sum_i fl(w_i^2) sequential
//   d = fp32-FMA dot;  dist = fl( fl(A - 2d) + C )
//   argmin: first index wins ties.

#define D    256
#define BT   128   // tokens per block
#define BC   128   // codes per chunk
#define BK   16    // k-slab
#define MAXN 65536
#define MAXE 4096

__device__ float g_A[MAXN];
__device__ float g_C[MAXE];
__device__ int   g_idx[MAXN];

// ---------------------------------------------------------------------------
// Row sum-of-squares, strictly sequential fp32 (square rounded, then added).
// 32 rows per block, staged through smem for coalesced global reads.
// which=1 -> g_A, which=0 -> g_C
// ---------------------------------------------------------------------------
__global__ void sumsq_kernel(const float* __restrict__ x, int which) {
    __shared__ float buf[32][257];   // +1 pad: conflict-free column walk
    int r0 = blockIdx.x * 32;
    for (int i = threadIdx.x; i < 32 * 256; i += 256) {
        int r = i >> 8, c = i & 255;
        buf[r][c] = x[(size_t)(r0 + r) * D + c];
    }
    __syncthreads();
    if (threadIdx.x < 32) {
        int r = threadIdx.x;
        float a = 0.0f;
        #pragma unroll 1
        for (int c = 0; c < 256; ++c) {
            float v = buf[r][c];
            a = __fadd_rn(a, __fmul_rn(v, v));   // no FMA contraction
        }
        if (which) g_A[r0 + r] = a;
        else       g_C[r0 + r] = a;
    }
}

// ---------------------------------------------------------------------------
// Fused GEMM + argmin. Block: 128 tokens x all NE codes (chunks of 128).
// 256 threads, 8x8 register tile each (16x16 thread grid).
// ---------------------------------------------------------------------------
__global__ void __launch_bounds__(256, 2)
vq_argmin_kernel(const float* __restrict__ z, const float* __restrict__ w, int ne) {
    __shared__ float sZ[BK][BT + 4];
    __shared__ float sW[BK][BC + 4];
    __shared__ float rD[BT][16];
    __shared__ int   rI[BT][16];

    const int tid = threadIdx.x;
    const int tx  = tid & 15;   // code group
    const int ty  = tid >> 4;   // token group
    const int bt0 = blockIdx.x * BT;

    float Ar[8];
    #pragma unroll
    for (int i = 0; i < 8; ++i) Ar[i] = g_A[bt0 + ty * 8 + i];

    float bd[8];
    int   bi[8];
    #pragma unroll
    for (int i = 0; i < 8; ++i) { bd[i] = __int_as_float(0x7f800000); bi[i] = 0x7fffffff; }

    for (int cc = 0; cc < ne; cc += BC) {
        float acc[8][8];
        #pragma unroll
        for (int i = 0; i < 8; ++i)
            #pragma unroll
            for (int j = 0; j < 8; ++j) acc[i][j] = 0.0f;

        float Cr[8];
        #pragma unroll
        for (int j = 0; j < 8; ++j) Cr[j] = g_C[cc + tx * 8 + j];

        for (int k0 = 0; k0 < D; k0 += BK) {
            __syncthreads();   // protect smem from previous slab's readers
            #pragma unroll
            for (int p = 0; p < 2; ++p) {
                int f4  = tid + p * 256;           // 512 float4s per tile
                int row = f4 >> 2;
                int kq  = (f4 & 3) * 4;
                float4 vz = *(const float4*)&z[(size_t)(bt0 + row) * D + k0 + kq];
                sZ[kq + 0][row] = vz.x; sZ[kq + 1][row] = vz.y;
                sZ[kq + 2][row] = vz.z; sZ[kq + 3][row] = vz.w;
                float4 vw = *(const float4*)&w[(size_t)(cc + row) * D + k0 + kq];
                sW[kq + 0][row] = vw.x; sW[kq + 1][row] = vw.y;
                sW[kq + 2][row] = vw.z; sW[kq + 3][row] = vw.w;
            }
            __syncthreads();

            #pragma unroll
            for (int kk = 0; kk < BK; ++kk) {
                float4 a0 = *(const float4*)&sZ[kk][ty * 8];
                float4 a1 = *(const float4*)&sZ[kk][ty * 8 + 4];
                float4 b0 = *(const float4*)&sW[kk][tx * 8];
                float4 b1 = *(const float4*)&sW[kk][tx * 8 + 4];
                float ar[8] = {a0.x, a0.y, a0.z, a0.w, a1.x, a1.y, a1.z, a1.w};
                float br[8] = {b0.x, b0.y, b0.z, b0.w, b1.x, b1.y, b1.z, b1.w};
                #pragma unroll
                for (int i = 0; i < 8; ++i)
                    #pragma unroll
                    for (int j = 0; j < 8; ++j)
                        acc[i][j] = fmaf(ar[i], br[j], acc[i][j]);
            }
        }

        // epilogue: dist = fl( fl(A - 2d) + C ), per-thread first-min
        #pragma unroll
        for (int i = 0; i < 8; ++i) {
            #pragma unroll
            for (int j = 0; j < 8; ++j) {
                float t1   = __fadd_rn(Ar[i], -2.0f * acc[i][j]);  // -2d exact
                float dist = __fadd_rn(t1, Cr[j]);
                int   cj   = cc + tx * 8 + j;                      // ascending in-thread
                if (dist < bd[i]) { bd[i] = dist; bi[i] = cj; }
            }
        }
    }

    // cross-thread reduce (16 threads per token), tie -> lower index
    #pragma unroll
    for (int i = 0; i < 8; ++i) { rD[ty * 8 + i][tx] = bd[i]; rI[ty * 8 + i][tx] = bi[i]; }
    __syncthreads();
    if (tid < BT) {
        float b = rD[tid][0];
        int   v = rI[tid][0];
        #pragma unroll
        for (int m = 1; m < 16; ++m) {
            float d = rD[tid][m];
            int   ii = rI[tid][m];
            if (d < b || (d == b && ii < v)) { b = d; v = ii; }
        }
        g_idx[bt0 + tid] = v;
    }
}

// ---------------------------------------------------------------------------
// Output: z_q_st = fl(z + fl(zq - z)); loss = fl(m + fl(0.25*m)), m = mean((zq-z)^2)
// one block (256 threads) per token.
// ---------------------------------------------------------------------------
__global__ void vq_out_kernel(const float* __restrict__ z, const float* __restrict__ w,
                              float* __restrict__ out_zq, float* __restrict__ out_loss,
                              float* __restrict__ out_idx) {
    __shared__ float red[8];
    const int t = blockIdx.x;
    const int e = threadIdx.x;
    const int j = g_idx[t];

    float zv = z[(size_t)t * D + e];
    float wv = w[(size_t)j * D + e];
    float d  = __fadd_rn(wv, -zv);
    out_zq[(size_t)t * D + e] = __fadd_rn(zv, d);

    float sq = __fmul_rn(d, d);
    #pragma unroll
    for (int o = 16; o > 0; o >>= 1) sq += __shfl_xor_sync(0xffffffffu, sq, o);
    if ((e & 31) == 0) red[e >> 5] = sq;
    __syncthreads();
    if (e == 0) {
        float s = 0.0f;
        #pragma unroll
        for (int wi = 0; wi < 8; ++wi) s += red[wi];
        float m = s * (1.0f / 256.0f);                     // /256 exact
        out_loss[t] = __fadd_rn(m, __fmul_rn(0.25f, m));
        out_idx[t]  = (float)j;
    }
}

// ---------------------------------------------------------------------------
extern "C" void kernel_launch(void* const* d_in, const int* in_sizes, int n_in,
                              void* d_out, int out_size) {
    const float* z = (const float*)d_in[0];
    const float* w = (const float*)d_in[1];
    const int n  = in_sizes[0] / D;   // 65536
    const int ne = in_sizes[1] / D;   // 1024
    float* out      = (float*)d_out;
    float* out_loss = out + (size_t)n * D;
    float* out_idx  = out_loss + n;

    sumsq_kernel<<<n / 32, 256>>>(z, 1);
    sumsq_kernel<<<ne / 32, 256>>>(w, 0);
    vq_argmin_kernel<<<n / BT, 256>>>(z, w, ne);
    vq_out_kernel<<<n, 256>>>(z, w, out, out_loss, out_idx);
}

// round 2
// speedup vs baseline: 1.0568x; 1.0568x over previous
#include <cuda_runtime.h>
#include <math.h>

// VectorQuantizer: z [N=65536, D=256] f32, codebook W [NE=1024, D=256] f32.
// dist = ||z||^2 - 2 z.W^T + ||w||^2 ; idx = argmin (first-min tie-break)
// outputs (concatenated float32): z_q_st [N*256] | loss [N] | idx [N]
//
// Precision contract: replicate reference fp32 rounding:
//   A = sum_i fl(z_i^2) sequential;  C = sum_i fl(w_i^2) sequential
//   d = fp32-FMA dot;  dist = fl( fl(A - 2d) + C )
//   argmin: first index wins ties.

#define D    256
#define BT   128   // tokens per block
#define BC   128   // codes per chunk
#define BK   16    // k-slab
#define MAXN 65536
#define MAXE 4096

__device__ float g_A[MAXN];
__device__ float g_C[MAXE];
__device__ int   g_idx[MAXN];

// ---------------------------------------------------------------------------
// Row sum-of-squares, strictly sequential fp32 (square rounded, then added).
// 32 rows per block, staged through smem for coalesced global reads.
// which=1 -> g_A, which=0 -> g_C
// ---------------------------------------------------------------------------
__global__ void sumsq_kernel(const float* __restrict__ x, int which) {
    __shared__ float buf[32][257];   // +1 pad: conflict-free column walk
    int r0 = blockIdx.x * 32;
    for (int i = threadIdx.x; i < 32 * 256; i += 256) {
        int r = i >> 8, c = i & 255;
        buf[r][c] = x[(size_t)(r0 + r) * D + c];
    }
    __syncthreads();
    if (threadIdx.x < 32) {
        int r = threadIdx.x;
        float a = 0.0f;
        #pragma unroll 1
        for (int c = 0; c < 256; ++c) {
            float v = buf[r][c];
            a = __fadd_rn(a, __fmul_rn(v, v));   // no FMA contraction
        }
        if (which) g_A[r0 + r] = a;
        else       g_C[r0 + r] = a;
    }
}

// ---------------------------------------------------------------------------
// Fused GEMM + argmin. Block: 128 tokens x all NE codes (chunks of 128).
// 256 threads, 8x8 register tile each (16x16 thread grid).
// ---------------------------------------------------------------------------
__global__ void __launch_bounds__(256, 2)
vq_argmin_kernel(const float* __restrict__ z, const float* __restrict__ w, int ne) {
    __shared__ float sZ[BK][BT + 4];
    __shared__ float sW[BK][BC + 4];
    __shared__ float rD[BT][16];
    __shared__ int   rI[BT][16];

    const int tid = threadIdx.x;
    const int tx  = tid & 15;   // code group
    const int ty  = tid >> 4;   // token group
    const int bt0 = blockIdx.x * BT;

    float Ar[8];
    #pragma unroll
    for (int i = 0; i < 8; ++i) Ar[i] = g_A[bt0 + ty * 8 + i];

    float bd[8];
    int   bi[8];
    #pragma unroll
    for (int i = 0; i < 8; ++i) { bd[i] = __int_as_float(0x7f800000); bi[i] = 0x7fffffff; }

    for (int cc = 0; cc < ne; cc += BC) {
        float acc[8][8];
        #pragma unroll
        for (int i = 0; i < 8; ++i)
            #pragma unroll
            for (int j = 0; j < 8; ++j) acc[i][j] = 0.0f;

        float Cr[8];
        #pragma unroll
        for (int j = 0; j < 8; ++j) Cr[j] = g_C[cc + tx * 8 + j];

        for (int k0 = 0; k0 < D; k0 += BK) {
            __syncthreads();   // protect smem from previous slab's readers
            #pragma unroll
            for (int p = 0; p < 2; ++p) {
                int f4  = tid + p * 256;           // 512 float4s per tile
                int row = f4 >> 2;
                int kq  = (f4 & 3) * 4;
                float4 vz = *(const float4*)&z[(size_t)(bt0 + row) * D + k0 + kq];
                sZ[kq + 0][row] = vz.x; sZ[kq + 1][row] = vz.y;
                sZ[kq + 2][row] = vz.z; sZ[kq + 3][row] = vz.w;
                float4 vw = *(const float4*)&w[(size_t)(cc + row) * D + k0 + kq];
                sW[kq + 0][row] = vw.x; sW[kq + 1][row] = vw.y;
                sW[kq + 2][row] = vw.z; sW[kq + 3][row] = vw.w;
            }
            __syncthreads();

            #pragma unroll
            for (int kk = 0; kk < BK; ++kk) {
                float4 a0 = *(const float4*)&sZ[kk][ty * 8];
                float4 a1 = *(const float4*)&sZ[kk][ty * 8 + 4];
                float4 b0 = *(const float4*)&sW[kk][tx * 8];
                float4 b1 = *(const float4*)&sW[kk][tx * 8 + 4];
                float ar[8] = {a0.x, a0.y, a0.z, a0.w, a1.x, a1.y, a1.z, a1.w};
                float br[8] = {b0.x, b0.y, b0.z, b0.w, b1.x, b1.y, b1.z, b1.w};
                #pragma unroll
                for (int i = 0; i < 8; ++i)
                    #pragma unroll
                    for (int j = 0; j < 8; ++j)
                        acc[i][j] = fmaf(ar[i], br[j], acc[i][j]);
            }
        }

        // epilogue: dist = fl( fl(A - 2d) + C ), per-thread first-min
        #pragma unroll
        for (int i = 0; i < 8; ++i) {
            #pragma unroll
            for (int j = 0; j < 8; ++j) {
                float t1   = __fadd_rn(Ar[i], -2.0f * acc[i][j]);  // -2d exact
                float dist = __fadd_rn(t1, Cr[j]);
                int   cj   = cc + tx * 8 + j;                      // ascending in-thread
                if (dist < bd[i]) { bd[i] = dist; bi[i] = cj; }
            }
        }
    }

    // cross-thread reduce (16 threads per token), tie -> lower index
    #pragma unroll
    for (int i = 0; i < 8; ++i) { rD[ty * 8 + i][tx] = bd[i]; rI[ty * 8 + i][tx] = bi[i]; }
    __syncthreads();
    if (tid < BT) {
        float b = rD[tid][0];
        int   v = rI[tid][0];
        #pragma unroll
        for (int m = 1; m < 16; ++m) {
            float d = rD[tid][m];
            int   ii = rI[tid][m];
            if (d < b || (d == b && ii < v)) { b = d; v = ii; }
        }
        g_idx[bt0 + tid] = v;
    }
}

// ---------------------------------------------------------------------------
// Output: z_q_st = fl(z + fl(zq - z)); loss = fl(m + fl(0.25*m)), m = mean((zq-z)^2)
// one block (256 threads) per token.
// ---------------------------------------------------------------------------
__global__ void vq_out_kernel(const float* __restrict__ z, const float* __restrict__ w,
                              float* __restrict__ out_zq, float* __restrict__ out_loss,
                              float* __restrict__ out_idx) {
    __shared__ float red[8];
    const int t = blockIdx.x;
    const int e = threadIdx.x;
    const int j = g_idx[t];

    float zv = z[(size_t)t * D + e];
    float wv = w[(size_t)j * D + e];
    float d  = __fadd_rn(wv, -zv);
    out_zq[(size_t)t * D + e] = __fadd_rn(zv, d);

    float sq = __fmul_rn(d, d);
    #pragma unroll
    for (int o = 16; o > 0; o >>= 1) sq += __shfl_xor_sync(0xffffffffu, sq, o);
    if ((e & 31) == 0) red[e >> 5] = sq;
    __syncthreads();
    if (e == 0) {
        float s = 0.0f;
        #pragma unroll
        for (int wi = 0; wi < 8; ++wi) s += red[wi];
        float m = s * (1.0f / 256.0f);                     // /256 exact
        out_loss[t] = __fadd_rn(m, __fmul_rn(0.25f, m));
        out_idx[t]  = (float)j;
    }
}

// ---------------------------------------------------------------------------
extern "C" void kernel_launch(void* const* d_in, const int* in_sizes, int n_in,
                              void* d_out, int out_size) {
    const float* z = (const float*)d_in[0];
    const float* w = (const float*)d_in[1];
    const int n  = in_sizes[0] / D;   // 65536
    const int ne = in_sizes[1] / D;   // 1024
    float* out      = (float*)d_out;
    float* out_loss = out + (size_t)n * D;
    float* out_idx  = out_loss + n;

    sumsq_kernel<<<n / 32, 256>>>(z, 1);
    sumsq_kernel<<<ne / 32, 256>>>(w, 0);
    vq_argmin_kernel<<<n / BT, 256>>>(z, w, ne);
    vq_out_kernel<<<n, 256>>>(z, w, out, out_loss, out_idx);
}